// round 16
// baseline (speedup 1.0000x reference)
#include <cuda_runtime.h>
#include <cuda_bf16.h>

// Single-pass fused blocked-scan RK4 on a 4-state LTI system.
// x_{t+1} = Phi x_t + Gam u_t (exact RK4 algebra for linear ODE + ZOH input).
//   k_init : 16-thread float build of Phi, Gam, M[s]=Phi^(16*2^s) s=0..17,
//            R[j] = rows 0,2 of Phi^(j+1); zero flags.
//   k_main : BLK=256, 5 blocks/SM co-resident (42KB smem, <=51 regs), 16 st/thr:
//            burst-load u tile -> phase1 STEP chain (slots overwritten with y)
//            -> warp KS scan (M[0..4]) + 8-warp agg scan (M[5..7]) -> publish
//            -> load-based lookback + 4-way fold (MB=M[8], powers M[8+s])
//            -> per-thread delta (8-bit tid powers) -> phase2 affine correction.

#define LSTEP 16
#define BLK 256
#define NWARP (BLK / 32)
#define MAXB 512
#define SU_STRIDE (BLK + 1)          // float2 row stride (pad kills bank conflicts)

__device__ float g_fPhi[16];
__device__ float g_fGam[8];
__device__ float g_fM[18][16];        // M[s] = Phi^(LSTEP * 2^s)
__device__ float g_fR[LSTEP][8];      // rows 0 and 2 of Phi^(j+1)
__device__ float4 g_agg[MAXB];
__device__ int g_flag[MAXB];

__global__ void k_init(const float* c, const float* m, const float* k,
                       const float* dtp) {
    __shared__ float sA[16], sP[16], sT[16], sR[16], sPhiD[16], sQ[16];
    int t = threadIdx.x;           // 16 threads
    int r = t >> 2, col = t & 3;

    for (int i = t; i < MAXB; i += 16) g_flag[i] = 0;

    float c1 = c[0], c2 = c[1], c3 = c[2];
    float m1 = m[0], m2 = m[1];
    float k1 = k[0], k2 = k[1], k3 = k[2];
    float h = dtp[0];

    if (t == 0) {
        sA[0] = 0.f;  sA[1] = 1.f;  sA[2] = 0.f;  sA[3] = 0.f;
        sA[4] = -(k1 + k2) / m1; sA[5] = -(c1 + c2) / m1; sA[6] = k2 / m1; sA[7] = c2 / m1;
        sA[8] = 0.f;  sA[9] = 0.f;  sA[10] = 0.f; sA[11] = 1.f;
        sA[12] = k2 / m2; sA[13] = c2 / m2; sA[14] = -(k3 + k2) / m2; sA[15] = -(c3 + c2) / m2;
    }
    __syncwarp(0xffffu);

    float id = (r == col) ? 1.f : 0.f;
    float h2 = h * h, h3 = h2 * h, h4 = h3 * h;
    float ph = id + h * sA[t];                 // Phi accumulator
    float g4 = h * id + (h2 / 2.f) * sA[t];    // G4 accumulator
    sP[t] = sA[t];
    __syncwarp(0xffffu);

    float coefP[3] = { h2 / 2.f, h3 / 6.f, h4 / 24.f };
    float coefG[2] = { h3 / 6.f, h4 / 24.f };
    for (int q = 0; q < 3; q++) {               // A^2, A^3, A^4
        float s = 0.f;
        for (int kk = 0; kk < 4; kk++) s = fmaf(sP[r * 4 + kk], sA[kk * 4 + col], s);
        __syncwarp(0xffffu);
        sP[t] = s;
        __syncwarp(0xffffu);
        ph = fmaf(coefP[q], s, ph);
        if (q < 2) g4 = fmaf(coefG[q], s, g4);
    }

    g_fPhi[t] = ph;
    sT[t] = g4;
    sPhiD[t] = ph;
    __syncwarp(0xffffu);
    if (t < 8) {   // Gam = G4 * B with B[1][0]=1/m1, B[3][1]=1/m2
        int rr = t >> 1, cc = t & 1;
        g_fGam[t] = sT[rr * 4 + (cc ? 3 : 1)] / (cc ? m2 : m1);
    }
    __syncwarp(0xffffu);

    // R[j] = rows 0,2 of Phi^(j+1):  Q = Phi; loop j: emit rows, Q = Q*Phi
    sQ[t] = ph;
    __syncwarp(0xffffu);
    for (int j = 0; j < LSTEP; j++) {
        if (r == 0) g_fR[j][col] = sQ[t];
        if (r == 2) g_fR[j][4 + col] = sQ[t];
        float s = 0.f;
        for (int kk = 0; kk < 4; kk++) s = fmaf(sQ[r * 4 + kk], sPhiD[kk * 4 + col], s);
        __syncwarp(0xffffu);
        sQ[t] = s;
        __syncwarp(0xffffu);
    }

    // sR = Phi^LSTEP (LSTEP=16 -> 4 squarings of Phi)
    sR[t] = ph;
    __syncwarp(0xffffu);
    for (int q = 0; q < 4; q++) {
        float s = 0.f;
        for (int kk = 0; kk < 4; kk++) s = fmaf(sR[r * 4 + kk], sR[kk * 4 + col], s);
        __syncwarp(0xffffu);
        sR[t] = s;
        __syncwarp(0xffffu);
    }
    g_fM[0][t] = sR[t];
    for (int ms = 1; ms < 18; ms++) {           // successive squarings
        float s = 0.f;
        for (int kk = 0; kk < 4; kk++) s = fmaf(sR[r * 4 + kk], sR[kk * 4 + col], s);
        __syncwarp(0xffffu);
        sR[t] = s;
        __syncwarp(0xffffu);
        g_fM[ms][t] = sR[t];
    }
}

#define STEP(ua, ub)                                                                         \
    do {                                                                                     \
        float n0 = fmaf(P[3],  x3, fmaf(P[2],  x2, fmaf(P[1],  x1, fmaf(P[0],  x0,          \
                   fmaf(G[1], (ub), G[0] * (ua))))));                                        \
        float n1 = fmaf(P[7],  x3, fmaf(P[6],  x2, fmaf(P[5],  x1, fmaf(P[4],  x0,          \
                   fmaf(G[3], (ub), G[2] * (ua))))));                                        \
        float n2 = fmaf(P[11], x3, fmaf(P[10], x2, fmaf(P[9],  x1, fmaf(P[8],  x0,          \
                   fmaf(G[5], (ub), G[4] * (ua))))));                                        \
        float n3 = fmaf(P[15], x3, fmaf(P[14], x2, fmaf(P[13], x1, fmaf(P[12], x0,          \
                   fmaf(G[7], (ub), G[6] * (ua))))));                                        \
        x0 = n0; x1 = n1; x2 = n2; x3 = n3;                                                  \
    } while (0)

// _v = M*_w + _v
#define AFF(Mm, _v, _w)                                                                      \
    do {                                                                                     \
        float n0 = fmaf(Mm[0],  (_w).x, fmaf(Mm[1],  (_w).y, fmaf(Mm[2],  (_w).z, fmaf(Mm[3],  (_w).w, (_v).x)))); \
        float n1 = fmaf(Mm[4],  (_w).x, fmaf(Mm[5],  (_w).y, fmaf(Mm[6],  (_w).z, fmaf(Mm[7],  (_w).w, (_v).y)))); \
        float n2 = fmaf(Mm[8],  (_w).x, fmaf(Mm[9],  (_w).y, fmaf(Mm[10], (_w).z, fmaf(Mm[11], (_w).w, (_v).z)))); \
        float n3 = fmaf(Mm[12], (_w).x, fmaf(Mm[13], (_w).y, fmaf(Mm[14], (_w).z, fmaf(Mm[15], (_w).w, (_v).w)))); \
        (_v).x = n0; (_v).y = n1; (_v).z = n2; (_v).w = n3;                                  \
    } while (0)

// _w = M*_w
#define MATP(Mm, _w)                                                                         \
    do {                                                                                     \
        float n0 = fmaf(Mm[0],  (_w).x, fmaf(Mm[1],  (_w).y, fmaf(Mm[2],  (_w).z, Mm[3]  * (_w).w))); \
        float n1 = fmaf(Mm[4],  (_w).x, fmaf(Mm[5],  (_w).y, fmaf(Mm[6],  (_w).z, Mm[7]  * (_w).w))); \
        float n2 = fmaf(Mm[8],  (_w).x, fmaf(Mm[9],  (_w).y, fmaf(Mm[10], (_w).z, Mm[11] * (_w).w))); \
        float n3 = fmaf(Mm[12], (_w).x, fmaf(Mm[13], (_w).y, fmaf(Mm[14], (_w).z, Mm[15] * (_w).w))); \
        (_w).x = n0; (_w).y = n1; (_w).z = n2; (_w).w = n3;                                  \
    } while (0)

#define SHFL_UP4(_d, _v, _w)                                                                 \
    do {                                                                                     \
        (_w).x = __shfl_up_sync(0xffffffffu, (_v).x, (_d));                                  \
        (_w).y = __shfl_up_sync(0xffffffffu, (_v).y, (_d));                                  \
        (_w).z = __shfl_up_sync(0xffffffffu, (_v).z, (_d));                                  \
        (_w).w = __shfl_up_sync(0xffffffffu, (_v).w, (_d));                                  \
    } while (0)

extern __shared__ float2 sU[];   // [LSTEP][SU_STRIDE]: u tile, overwritten with (z1,z2)

__global__ void __launch_bounds__(BLK, 5) k_main(const float* __restrict__ u,
                                                 const float* __restrict__ x0in,
                                                 float* __restrict__ out, int T) {
    __shared__ float sM[18][16];
    __shared__ float sR2[LSTEP][8];
    __shared__ float4 sWagg[NWARP];
    __shared__ float4 sWscan[NWARP];
    __shared__ float4 sAgg[MAXB];
    __shared__ float4 sF[4];
    __shared__ int sLen[4];
    __shared__ float4 sPref;

    int tid = threadIdx.x;
    int lane = tid & 31, wrp = tid >> 5;
    int b = blockIdx.x;
    int p = b * BLK + tid;

    if (tid < 160) ((float*)sM)[tid] = ((const float*)g_fM)[tid];
    else if (tid < 160 + 128) ((float*)g_fM, ((float*)sM)[tid] = ((const float*)g_fM)[tid]);
    // (two halves: 288 floats total, BLK=256 -> second pass below)
    if (tid < 32) ((float*)sM)[256 + tid] = ((const float*)g_fM)[256 + tid];
    if (tid >= 64 && tid < 64 + 8 * LSTEP)
        ((float*)sR2)[tid - 64] = ((const float*)g_fR)[tid - 64];

    float P[16], G[8];
#pragma unroll
    for (int i = 0; i < 16; i++) P[i] = g_fPhi[i];
#pragma unroll
    for (int i = 0; i < 8; i++) G[i] = g_fGam[i];

    // ---- coalesced burst load of this block's u tile into smem (MLP 8) ----
    {
        const float4* ug = (const float4*)u;
        int base4 = b * (BLK * LSTEP / 2);        // 2048 float4 per block
        int uTot = 2 * T;                         // floats in u
#pragma unroll
        for (int cny = 0; cny < 8; cny++) {
            int f = cny * BLK + tid;              // 0..2047
            int gf = base4 + f;
            float4 a = make_float4(0.f, 0.f, 0.f, 0.f);
            if (4 * gf + 4 <= uTot) {
                a = ug[gf];
            } else if (4 * gf < uTot) {           // ragged boundary
                const float* us = u + 4 * gf;
                int n = uTot - 4 * gf;
                a.x = us[0];
                if (n > 1) a.y = us[1];
                if (n > 2) a.z = us[2];
            }
            int owner = f >> 3;
            int row = 2 * (f & 7);
            sU[row * SU_STRIDE + owner] = make_float2(a.x, a.y);
            sU[(row + 1) * SU_STRIDE + owner] = make_float2(a.z, a.w);
        }
    }
    __syncthreads();                              // sM, sR2, sU ready

    int t0 = p * LSTEP;
    int te = t0 + LSTEP; if (te > T) te = T;
    int rem = te - t0; if (rem < 0) rem = 0;      // steps this thread owns (0..16)

    // ---- phase 1: STEP chain from 0 (chain 0 from x0); overwrite slots with y ----
    float x0 = 0.f, x1 = 0.f, x2 = 0.f, x3 = 0.f;
    if (p == 0) { x0 = x0in[0]; x1 = x0in[1]; x2 = x0in[2]; x3 = x0in[3]; }
    if (rem == LSTEP) {
#pragma unroll
        for (int j = 0; j < LSTEP; j++) {
            float2 uu = sU[j * SU_STRIDE + tid];
            STEP(uu.x, uu.y);
            sU[j * SU_STRIDE + tid] = make_float2(x0, x2);
        }
    } else if (rem > 0) {
        for (int j = 0; j < rem; j++) {
            float2 uu = sU[j * SU_STRIDE + tid];
            STEP(uu.x, uu.y);
            sU[j * SU_STRIDE + tid] = make_float2(x0, x2);
        }
    }
    float4 v = make_float4(x0, x1, x2, x3);

    // ---- warp Kogge-Stone scan (shuffles; M[0..4]) ----
#pragma unroll
    for (int s = 0; s < 5; s++) {
        int d = 1 << s;
        float4 w;
        SHFL_UP4(d, v, w);
        if (lane >= d) { const float* M = sM[s]; AFF(M, v, w); }
    }
    float4 ev;                                     // exclusive within-warp scan
    SHFL_UP4(1, v, ev);
    if (lane == 0) ev = make_float4(0.f, 0.f, 0.f, 0.f);
    if (lane == 31) sWagg[wrp] = v;
    __syncthreads();

    // ---- warp 0 scans the NWARP=8 warp aggregates (M[5..7]) ----
    // ALL 32 lanes execute the shuffles (full-mask safety); lanes >= NWARP
    // work on a clamped dummy value and never write.
    if (wrp == 0) {
        float4 av = sWagg[lane < NWARP ? lane : (NWARP - 1)];
#pragma unroll
        for (int s = 0; s < 3; s++) {
            int d = 1 << s;
            float4 w;
            SHFL_UP4(d, av, w);
            if (lane >= d && lane < NWARP) { const float* M = sM[5 + s]; AFF(M, av, w); }
        }
        if (lane < NWARP) sWscan[lane] = av;
    }
    __syncthreads();

    // ---- publish block aggregate ----
    if (tid == 0) {
        g_agg[b] = sWscan[NWARP - 1];
        __threadfence();
        atomicExch(&g_flag[b], 1);
    }

    // ---- lookback: warp 0 polls with plain volatile loads ----
    if (wrp == 0) {
        volatile int* vf = g_flag;
        for (int j = lane; j < b; j += 32) {
            while (vf[j] == 0) { }
        }
        __threadfence();                           // acquire before reading g_agg
    }
    __syncthreads();
    // cooperative load of previous aggregates via L2 (bypass L1 staleness)
    for (int j = tid; j < b; j += BLK) {
        const float4* src = &g_agg[j];
        float4 a;
        asm volatile("ld.global.cg.v4.f32 {%0,%1,%2,%3}, [%4];"
                     : "=f"(a.x), "=f"(a.y), "=f"(a.z), "=f"(a.w) : "l"(src));
        sAgg[j] = a;
    }
    __syncthreads();

    // ---- 4-way parallel fold: Pref_b = sum_{j<b} MB^{b-1-j} S_j, MB = M[8] ----
    const float* MB = sM[8];
    if (tid < 4) {
        int q = (b + 3) >> 2;
        int j0 = tid * q, j1 = j0 + q; if (j1 > b) j1 = b; if (j0 > b) j0 = b;
        float4 F = make_float4(0.f, 0.f, 0.f, 0.f);
        for (int j = j0; j < j1; j++) {
            float4 S = sAgg[j];
            MATP(MB, F);
            F.x += S.x; F.y += S.y; F.z += S.z; F.w += S.w;
        }
        sF[tid] = F; sLen[tid] = j1 - j0;
    }
    __syncthreads();
    if (tid == 0) {
        float4 acc = (b > 0) ? sF[0] : make_float4(0.f, 0.f, 0.f, 0.f);
#pragma unroll
        for (int l = 1; l < 4; l++) {
            int r = sLen[l];
#pragma unroll
            for (int s = 0; s < 8; s++)                 // r < 128, 8 bits safe
                if ((r >> s) & 1) { const float* M = sM[8 + s]; MATP(M, acc); }
            float4 F = sF[l];
            acc.x += F.x; acc.y += F.y; acc.z += F.z; acc.w += F.w;
        }
        sPref = acc;
    }
    __syncthreads();

    if (rem == 0) return;   // all barriers done; idle tail threads exit

    // ---- per-thread start delta d (d = x_start - phase1 start; 0 for p==0) ----
    float4 d4 = make_float4(0.f, 0.f, 0.f, 0.f);
    if (p != 0) {
        if (b > 0) {
            d4 = sPref;
#pragma unroll
            for (int s = 0; s < 8; s++)                 // tid < 256 -> 8 bits
                if ((tid >> s) & 1) { const float* M = sM[s]; MATP(M, d4); }
        }
        if (wrp > 0) {
            float4 wp = sWscan[wrp - 1];
#pragma unroll
            for (int s = 0; s < 5; s++)
                if ((lane >> s) & 1) { const float* M = sM[s]; MATP(M, wp); }
            d4.x += wp.x; d4.y += wp.y; d4.z += wp.z; d4.w += wp.w;
        }
        d4.x += ev.x; d4.y += ev.y; d4.z += ev.z; d4.w += ev.w;
    }

    // ---- phase 2: out_j = y_j + R[j] * d   (no serial chain, no u re-read) ----
    if (rem == LSTEP) {
        float4* o4 = (float4*)(out + 2 * t0);
#pragma unroll
        for (int j = 0; j < LSTEP / 2; j++) {
            float2 ya = sU[(2 * j) * SU_STRIDE + tid];
            float2 yb = sU[(2 * j + 1) * SU_STRIDE + tid];
            const float* Ra = sR2[2 * j];
            const float* Rb = sR2[2 * j + 1];
            float z1a = fmaf(Ra[0], d4.x, fmaf(Ra[1], d4.y, fmaf(Ra[2], d4.z, fmaf(Ra[3], d4.w, ya.x))));
            float z2a = fmaf(Ra[4], d4.x, fmaf(Ra[5], d4.y, fmaf(Ra[6], d4.z, fmaf(Ra[7], d4.w, ya.y))));
            float z1b = fmaf(Rb[0], d4.x, fmaf(Rb[1], d4.y, fmaf(Rb[2], d4.z, fmaf(Rb[3], d4.w, yb.x))));
            float z2b = fmaf(Rb[4], d4.x, fmaf(Rb[5], d4.y, fmaf(Rb[6], d4.z, fmaf(Rb[7], d4.w, yb.y))));
            o4[j] = make_float4(z1a, z2a, z1b, z2b);
        }
    } else {
        for (int j = 0; j < rem; j++) {
            float2 y = sU[j * SU_STRIDE + tid];
            const float* R = sR2[j];
            float z1 = fmaf(R[0], d4.x, fmaf(R[1], d4.y, fmaf(R[2], d4.z, fmaf(R[3], d4.w, y.x))));
            float z2 = fmaf(R[4], d4.x, fmaf(R[5], d4.y, fmaf(R[6], d4.z, fmaf(R[7], d4.w, y.y))));
            *(float2*)(out + 2 * (t0 + j)) = make_float2(z1, z2);
        }
    }
}

extern "C" void kernel_launch(void* const* d_in, const int* in_sizes, int n_in,
                              void* d_out, int out_size) {
    const float* u  = (const float*)d_in[0];
    const float* x0 = (const float*)d_in[1];
    const float* c  = (const float*)d_in[2];
    const float* m  = (const float*)d_in[3];
    const float* k  = (const float*)d_in[4];
    const float* dt = (const float*)d_in[5];
    float* out = (float*)d_out;

    int T = in_sizes[0] / 2;
    int chains = (T + LSTEP - 1) / LSTEP;
    int grid = (chains + BLK - 1) / BLK;     // 489 for T = 2e6; 5/SM -> single wave

    size_t dynSmem = (size_t)LSTEP * SU_STRIDE * sizeof(float2);   // ~33 KB
    cudaFuncSetAttribute(k_main, cudaFuncAttributeMaxDynamicSharedMemorySize,
                         (int)dynSmem);

    k_init<<<1, 16>>>(c, m, k, dt);
    k_main<<<grid, BLK, dynSmem>>>(u, x0, out, T);
}

// round 17
// speedup vs baseline: 1.0654x; 1.0654x over previous
#include <cuda_runtime.h>
#include <cuda_bf16.h>

// Single-pass fused blocked-scan RK4 on a 4-state LTI system.
// x_{t+1} = Phi x_t + Gam u_t (exact RK4 algebra for linear ODE + ZOH input).
//   k_init : 16-thread float build of Phi, Gam, M[s]=Phi^(16*2^s) s=0..17,
//            R[j] = rows 0,2 of Phi^(j+1); zero flags.
//   k_main : BLK=512, 2 blocks/SM, 16 steps/thread:
//            burst-load u tile -> phase1 STEP chain (prefetch-pipelined LDS)
//            -> warp KS scan (M[0..4]) + 16-warp agg scan (M[5..8]) -> publish
//            -> load-based lookback -> PARALLEL fold: per-thread binary powers
//               of MB=M[9] (M[9+s] table) + block-wide float4 sum reduction
//            -> per-thread delta -> phase2 affine correction.

#define LSTEP 16
#define BLK 512
#define NWARP (BLK / 32)
#define MAXB 512
#define SU_STRIDE (BLK + 1)          // float2 row stride (pad kills bank conflicts)

__device__ float g_fPhi[16];
__device__ float g_fGam[8];
__device__ float g_fM[18][16];        // M[s] = Phi^(LSTEP * 2^s)
__device__ float g_fR[LSTEP][8];      // rows 0 and 2 of Phi^(j+1)
__device__ float4 g_agg[MAXB];
__device__ int g_flag[MAXB];

__global__ void k_init(const float* c, const float* m, const float* k,
                       const float* dtp) {
    __shared__ float sA[16], sP[16], sT[16], sR[16], sPhiD[16], sQ[16];
    int t = threadIdx.x;           // 16 threads
    int r = t >> 2, col = t & 3;

    for (int i = t; i < MAXB; i += 16) g_flag[i] = 0;

    float c1 = c[0], c2 = c[1], c3 = c[2];
    float m1 = m[0], m2 = m[1];
    float k1 = k[0], k2 = k[1], k3 = k[2];
    float h = dtp[0];

    if (t == 0) {
        sA[0] = 0.f;  sA[1] = 1.f;  sA[2] = 0.f;  sA[3] = 0.f;
        sA[4] = -(k1 + k2) / m1; sA[5] = -(c1 + c2) / m1; sA[6] = k2 / m1; sA[7] = c2 / m1;
        sA[8] = 0.f;  sA[9] = 0.f;  sA[10] = 0.f; sA[11] = 1.f;
        sA[12] = k2 / m2; sA[13] = c2 / m2; sA[14] = -(k3 + k2) / m2; sA[15] = -(c3 + c2) / m2;
    }
    __syncwarp(0xffffu);

    float id = (r == col) ? 1.f : 0.f;
    float h2 = h * h, h3 = h2 * h, h4 = h3 * h;
    float ph = id + h * sA[t];                 // Phi accumulator
    float g4 = h * id + (h2 / 2.f) * sA[t];    // G4 accumulator
    sP[t] = sA[t];
    __syncwarp(0xffffu);

    float coefP[3] = { h2 / 2.f, h3 / 6.f, h4 / 24.f };
    float coefG[2] = { h3 / 6.f, h4 / 24.f };
    for (int q = 0; q < 3; q++) {               // A^2, A^3, A^4
        float s = 0.f;
        for (int kk = 0; kk < 4; kk++) s = fmaf(sP[r * 4 + kk], sA[kk * 4 + col], s);
        __syncwarp(0xffffu);
        sP[t] = s;
        __syncwarp(0xffffu);
        ph = fmaf(coefP[q], s, ph);
        if (q < 2) g4 = fmaf(coefG[q], s, g4);
    }

    g_fPhi[t] = ph;
    sT[t] = g4;
    sPhiD[t] = ph;
    __syncwarp(0xffffu);
    if (t < 8) {   // Gam = G4 * B with B[1][0]=1/m1, B[3][1]=1/m2
        int rr = t >> 1, cc = t & 1;
        g_fGam[t] = sT[rr * 4 + (cc ? 3 : 1)] / (cc ? m2 : m1);
    }
    __syncwarp(0xffffu);

    // R[j] = rows 0,2 of Phi^(j+1):  Q = Phi; loop j: emit rows, Q = Q*Phi
    sQ[t] = ph;
    __syncwarp(0xffffu);
    for (int j = 0; j < LSTEP; j++) {
        if (r == 0) g_fR[j][col] = sQ[t];
        if (r == 2) g_fR[j][4 + col] = sQ[t];
        float s = 0.f;
        for (int kk = 0; kk < 4; kk++) s = fmaf(sQ[r * 4 + kk], sPhiD[kk * 4 + col], s);
        __syncwarp(0xffffu);
        sQ[t] = s;
        __syncwarp(0xffffu);
    }

    // sR = Phi^LSTEP (LSTEP=16 -> 4 squarings of Phi)
    sR[t] = ph;
    __syncwarp(0xffffu);
    for (int q = 0; q < 4; q++) {
        float s = 0.f;
        for (int kk = 0; kk < 4; kk++) s = fmaf(sR[r * 4 + kk], sR[kk * 4 + col], s);
        __syncwarp(0xffffu);
        sR[t] = s;
        __syncwarp(0xffffu);
    }
    g_fM[0][t] = sR[t];
    for (int ms = 1; ms < 18; ms++) {           // successive squarings
        float s = 0.f;
        for (int kk = 0; kk < 4; kk++) s = fmaf(sR[r * 4 + kk], sR[kk * 4 + col], s);
        __syncwarp(0xffffu);
        sR[t] = s;
        __syncwarp(0xffffu);
        g_fM[ms][t] = sR[t];
    }
}

#define STEP(ua, ub)                                                                         \
    do {                                                                                     \
        float n0 = fmaf(P[3],  x3, fmaf(P[2],  x2, fmaf(P[1],  x1, fmaf(P[0],  x0,          \
                   fmaf(G[1], (ub), G[0] * (ua))))));                                        \
        float n1 = fmaf(P[7],  x3, fmaf(P[6],  x2, fmaf(P[5],  x1, fmaf(P[4],  x0,          \
                   fmaf(G[3], (ub), G[2] * (ua))))));                                        \
        float n2 = fmaf(P[11], x3, fmaf(P[10], x2, fmaf(P[9],  x1, fmaf(P[8],  x0,          \
                   fmaf(G[5], (ub), G[4] * (ua))))));                                        \
        float n3 = fmaf(P[15], x3, fmaf(P[14], x2, fmaf(P[13], x1, fmaf(P[12], x0,          \
                   fmaf(G[7], (ub), G[6] * (ua))))));                                        \
        x0 = n0; x1 = n1; x2 = n2; x3 = n3;                                                  \
    } while (0)

// _v = M*_w + _v
#define AFF(Mm, _v, _w)                                                                      \
    do {                                                                                     \
        float n0 = fmaf(Mm[0],  (_w).x, fmaf(Mm[1],  (_w).y, fmaf(Mm[2],  (_w).z, fmaf(Mm[3],  (_w).w, (_v).x)))); \
        float n1 = fmaf(Mm[4],  (_w).x, fmaf(Mm[5],  (_w).y, fmaf(Mm[6],  (_w).z, fmaf(Mm[7],  (_w).w, (_v).y)))); \
        float n2 = fmaf(Mm[8],  (_w).x, fmaf(Mm[9],  (_w).y, fmaf(Mm[10], (_w).z, fmaf(Mm[11], (_w).w, (_v).z)))); \
        float n3 = fmaf(Mm[12], (_w).x, fmaf(Mm[13], (_w).y, fmaf(Mm[14], (_w).z, fmaf(Mm[15], (_w).w, (_v).w)))); \
        (_v).x = n0; (_v).y = n1; (_v).z = n2; (_v).w = n3;                                  \
    } while (0)

// _w = M*_w
#define MATP(Mm, _w)                                                                         \
    do {                                                                                     \
        float n0 = fmaf(Mm[0],  (_w).x, fmaf(Mm[1],  (_w).y, fmaf(Mm[2],  (_w).z, Mm[3]  * (_w).w))); \
        float n1 = fmaf(Mm[4],  (_w).x, fmaf(Mm[5],  (_w).y, fmaf(Mm[6],  (_w).z, Mm[7]  * (_w).w))); \
        float n2 = fmaf(Mm[8],  (_w).x, fmaf(Mm[9],  (_w).y, fmaf(Mm[10], (_w).z, Mm[11] * (_w).w))); \
        float n3 = fmaf(Mm[12], (_w).x, fmaf(Mm[13], (_w).y, fmaf(Mm[14], (_w).z, Mm[15] * (_w).w))); \
        (_w).x = n0; (_w).y = n1; (_w).z = n2; (_w).w = n3;                                  \
    } while (0)

#define SHFL_UP4(_d, _v, _w)                                                                 \
    do {                                                                                     \
        (_w).x = __shfl_up_sync(0xffffffffu, (_v).x, (_d));                                  \
        (_w).y = __shfl_up_sync(0xffffffffu, (_v).y, (_d));                                  \
        (_w).z = __shfl_up_sync(0xffffffffu, (_v).z, (_d));                                  \
        (_w).w = __shfl_up_sync(0xffffffffu, (_v).w, (_d));                                  \
    } while (0)

#define SHFL_DN4_ADD(_d, _v)                                                                 \
    do {                                                                                     \
        (_v).x += __shfl_down_sync(0xffffffffu, (_v).x, (_d));                               \
        (_v).y += __shfl_down_sync(0xffffffffu, (_v).y, (_d));                               \
        (_v).z += __shfl_down_sync(0xffffffffu, (_v).z, (_d));                               \
        (_v).w += __shfl_down_sync(0xffffffffu, (_v).w, (_d));                               \
    } while (0)

extern __shared__ float2 sU[];   // [LSTEP][SU_STRIDE]: u tile, overwritten with (z1,z2)

__global__ void __launch_bounds__(BLK, 2) k_main(const float* __restrict__ u,
                                                 const float* __restrict__ x0in,
                                                 float* __restrict__ out, int T) {
    __shared__ float sM[18][16];
    __shared__ float sR2[LSTEP][8];
    __shared__ float4 sWagg[NWARP];
    __shared__ float4 sWscan[NWARP];
    __shared__ float4 sWred[NWARP];
    __shared__ float4 sPref;

    int tid = threadIdx.x;
    int lane = tid & 31, wrp = tid >> 5;
    int b = blockIdx.x;
    int p = b * BLK + tid;

    if (tid < 288) ((float*)sM)[tid] = ((const float*)g_fM)[tid];
    else if (tid >= 320 && tid < 320 + 8 * LSTEP)
        ((float*)sR2)[tid - 320] = ((const float*)g_fR)[tid - 320];

    float P[16], G[8];
#pragma unroll
    for (int i = 0; i < 16; i++) P[i] = g_fPhi[i];
#pragma unroll
    for (int i = 0; i < 8; i++) G[i] = g_fGam[i];

    // ---- coalesced burst load of this block's u tile into smem (MLP 8) ----
    {
        const float4* ug = (const float4*)u;
        int base4 = b * (BLK * LSTEP / 2);        // 4096 float4 per block
        int uTot = 2 * T;                         // floats in u
#pragma unroll
        for (int cny = 0; cny < 8; cny++) {
            int f = cny * BLK + tid;              // 0..4095
            int gf = base4 + f;
            float4 a = make_float4(0.f, 0.f, 0.f, 0.f);
            if (4 * gf + 4 <= uTot) {
                a = ug[gf];
            } else if (4 * gf < uTot) {           // ragged boundary
                const float* us = u + 4 * gf;
                int n = uTot - 4 * gf;
                a.x = us[0];
                if (n > 1) a.y = us[1];
                if (n > 2) a.z = us[2];
            }
            int owner = f >> 3;
            int row = 2 * (f & 7);
            sU[row * SU_STRIDE + owner] = make_float2(a.x, a.y);
            sU[(row + 1) * SU_STRIDE + owner] = make_float2(a.z, a.w);
        }
    }
    __syncthreads();                              // sM, sR2, sU ready

    int t0 = p * LSTEP;
    int te = t0 + LSTEP; if (te > T) te = T;
    int rem = te - t0; if (rem < 0) rem = 0;      // steps this thread owns (0..16)

    // ---- phase 1: STEP chain from 0 (chain 0 from x0); LDS prefetch pipeline ----
    float x0 = 0.f, x1 = 0.f, x2 = 0.f, x3 = 0.f;
    if (p == 0) { x0 = x0in[0]; x1 = x0in[1]; x2 = x0in[2]; x3 = x0in[3]; }
    if (rem == LSTEP) {
        float2 uu = sU[tid];
#pragma unroll
        for (int j = 0; j < LSTEP; j++) {
            float2 un = (j + 1 < LSTEP) ? sU[(j + 1) * SU_STRIDE + tid] : uu;
            STEP(uu.x, uu.y);
            sU[j * SU_STRIDE + tid] = make_float2(x0, x2);
            uu = un;
        }
    } else if (rem > 0) {
        for (int j = 0; j < rem; j++) {
            float2 uu = sU[j * SU_STRIDE + tid];
            STEP(uu.x, uu.y);
            sU[j * SU_STRIDE + tid] = make_float2(x0, x2);
        }
    }
    float4 v = make_float4(x0, x1, x2, x3);

    // ---- warp Kogge-Stone scan (shuffles; M[0..4]) ----
#pragma unroll
    for (int s = 0; s < 5; s++) {
        int d = 1 << s;
        float4 w;
        SHFL_UP4(d, v, w);
        if (lane >= d) { const float* M = sM[s]; AFF(M, v, w); }
    }
    float4 ev;                                     // exclusive within-warp scan
    SHFL_UP4(1, v, ev);
    if (lane == 0) ev = make_float4(0.f, 0.f, 0.f, 0.f);
    if (lane == 31) sWagg[wrp] = v;
    __syncthreads();

    // ---- warp 0 scans the NWARP=16 warp aggregates (M[5..8]) ----
    if (wrp == 0) {
        float4 av = sWagg[lane < NWARP ? lane : (NWARP - 1)];
#pragma unroll
        for (int s = 0; s < 4; s++) {
            int d = 1 << s;
            float4 w;
            SHFL_UP4(d, av, w);
            if (lane >= d && lane < NWARP) { const float* M = sM[5 + s]; AFF(M, av, w); }
        }
        if (lane < NWARP) sWscan[lane] = av;
    }
    __syncthreads();

    // ---- publish block aggregate ----
    if (tid == 0) {
        g_agg[b] = sWscan[NWARP - 1];
        __threadfence();
        atomicExch(&g_flag[b], 1);
    }

    // ---- lookback: warp 0 polls with plain volatile loads ----
    if (wrp == 0) {
        volatile int* vf = g_flag;
        for (int j = lane; j < b; j += 32) {
            while (vf[j] == 0) { }
        }
        __threadfence();                           // acquire before reading g_agg
    }
    __syncthreads();

    // ---- PARALLEL fold: thread j computes MB^(b-1-j) * S_j, block-sums ----
    //      MB^(2^s) = M[9+s], s = 0..8 (exponent b-1-j < 511)
    float4 term = make_float4(0.f, 0.f, 0.f, 0.f);
    if (tid < b) {
        const float4* src = &g_agg[tid];
        asm volatile("ld.global.cg.v4.f32 {%0,%1,%2,%3}, [%4];"
                     : "=f"(term.x), "=f"(term.y), "=f"(term.z), "=f"(term.w) : "l"(src));
        int e = b - 1 - tid;
#pragma unroll
        for (int s = 0; s < 9; s++)
            if ((e >> s) & 1) { const float* M = sM[9 + s]; MATP(M, term); }
    }
    // block-wide float4 sum reduction
#pragma unroll
    for (int d = 16; d > 0; d >>= 1) SHFL_DN4_ADD(d, term);
    if (lane == 0) sWred[wrp] = term;
    __syncthreads();
    if (wrp == 0) {
        float4 acc = (lane < NWARP) ? sWred[lane] : make_float4(0.f, 0.f, 0.f, 0.f);
#pragma unroll
        for (int d = 8; d > 0; d >>= 1) SHFL_DN4_ADD(d, acc);
        if (lane == 0) sPref = acc;
    }
    __syncthreads();

    if (rem == 0) return;   // all barriers done; idle tail threads exit

    // ---- per-thread start delta d (d = x_start - phase1 start; 0 for p==0) ----
    float4 d4 = make_float4(0.f, 0.f, 0.f, 0.f);
    if (p != 0) {
        if (b > 0) {
            d4 = sPref;
#pragma unroll
            for (int s = 0; s < 9; s++)                 // tid < 512 -> 9 bits
                if ((tid >> s) & 1) { const float* M = sM[s]; MATP(M, d4); }
        }
        if (wrp > 0) {
            float4 wp = sWscan[wrp - 1];
#pragma unroll
            for (int s = 0; s < 5; s++)
                if ((lane >> s) & 1) { const float* M = sM[s]; MATP(M, wp); }
            d4.x += wp.x; d4.y += wp.y; d4.z += wp.z; d4.w += wp.w;
        }
        d4.x += ev.x; d4.y += ev.y; d4.z += ev.z; d4.w += ev.w;
    }

    // ---- phase 2: out_j = y_j + R[j] * d   (no serial chain, no u re-read) ----
    if (rem == LSTEP) {
        float4* o4 = (float4*)(out + 2 * t0);
#pragma unroll
        for (int j = 0; j < LSTEP / 2; j++) {
            float2 ya = sU[(2 * j) * SU_STRIDE + tid];
            float2 yb = sU[(2 * j + 1) * SU_STRIDE + tid];
            const float* Ra = sR2[2 * j];
            const float* Rb = sR2[2 * j + 1];
            float z1a = fmaf(Ra[0], d4.x, fmaf(Ra[1], d4.y, fmaf(Ra[2], d4.z, fmaf(Ra[3], d4.w, ya.x))));
            float z2a = fmaf(Ra[4], d4.x, fmaf(Ra[5], d4.y, fmaf(Ra[6], d4.z, fmaf(Ra[7], d4.w, ya.y))));
            float z1b = fmaf(Rb[0], d4.x, fmaf(Rb[1], d4.y, fmaf(Rb[2], d4.z, fmaf(Rb[3], d4.w, yb.x))));
            float z2b = fmaf(Rb[4], d4.x, fmaf(Rb[5], d4.y, fmaf(Rb[6], d4.z, fmaf(Rb[7], d4.w, yb.y))));
            o4[j] = make_float4(z1a, z2a, z1b, z2b);
        }
    } else {
        for (int j = 0; j < rem; j++) {
            float2 y = sU[j * SU_STRIDE + tid];
            const float* R = sR2[j];
            float z1 = fmaf(R[0], d4.x, fmaf(R[1], d4.y, fmaf(R[2], d4.z, fmaf(R[3], d4.w, y.x))));
            float z2 = fmaf(R[4], d4.x, fmaf(R[5], d4.y, fmaf(R[6], d4.z, fmaf(R[7], d4.w, y.y))));
            *(float2*)(out + 2 * (t0 + j)) = make_float2(z1, z2);
        }
    }
}

extern "C" void kernel_launch(void* const* d_in, const int* in_sizes, int n_in,
                              void* d_out, int out_size) {
    const float* u  = (const float*)d_in[0];
    const float* x0 = (const float*)d_in[1];
    const float* c  = (const float*)d_in[2];
    const float* m  = (const float*)d_in[3];
    const float* k  = (const float*)d_in[4];
    const float* dt = (const float*)d_in[5];
    float* out = (float*)d_out;

    int T = in_sizes[0] / 2;
    int chains = (T + LSTEP - 1) / LSTEP;
    int grid = (chains + BLK - 1) / BLK;     // 245 for T = 2e6; 2/SM -> single wave

    size_t dynSmem = (size_t)LSTEP * SU_STRIDE * sizeof(float2);   // ~65.7 KB
    cudaFuncSetAttribute(k_main, cudaFuncAttributeMaxDynamicSharedMemorySize,
                         (int)dynSmem);

    k_init<<<1, 16>>>(c, m, k, dt);
    k_main<<<grid, BLK, dynSmem>>>(u, x0, out, T);
}